// round 14
// baseline (speedup 1.0000x reference)
#include <cuda_runtime.h>
#include <cstdint>

#define K_DIM 7168
#define N_DIM 256
#define BM 128
#define NKB 56
#define THREADS 512

// smem layout (bytes): ws | act-scales | A(2 stages) | B(2) | X(2)
#define OFF_WS 0              // 112 f32 weight scales (512B)
#define OFF_SC 512            // 2 x 128 f32 act scales (1024B)
#define OFF_A  1536           // 2 x 16384 (128 rows x 128B, swizzled)
#define OFF_B  34304          // 2 x 32768 (256 rows x 128B, swizzled)
#define OFF_X  99840          // 2 x 65536 (128 rows x 512B f32, swizzled)
#define SMEM_BYTES 230912

__device__ __align__(16) uint8_t g_w8[(size_t)N_DIM * K_DIM];

// ---------------- helpers ----------------

__device__ __forceinline__ uint32_t q2(float a, float b, float inv) {
    uint16_t p;
    asm("cvt.rn.satfinite.e4m3x2.f32 %0, %1, %2;"
        : "=h"(p) : "f"(b * inv), "f"(a * inv));
    return (uint32_t)p;
}

__device__ __forceinline__ void qmma(float* c, const uint32_t* a,
                                     uint32_t b0, uint32_t b1) {
    asm volatile(
        "mma.sync.aligned.m16n8k32.row.col.f32.e4m3.e4m3.f32 "
        "{%0,%1,%2,%3}, {%4,%5,%6,%7}, {%8,%9}, {%0,%1,%2,%3};"
        : "+f"(c[0]), "+f"(c[1]), "+f"(c[2]), "+f"(c[3])
        : "r"(a[0]), "r"(a[1]), "r"(a[2]), "r"(a[3]), "r"(b0), "r"(b1));
}

#define LDSM4(r0, r1, r2, r3, addr)                                        \
    asm volatile("ldmatrix.sync.aligned.m8n8.x4.shared.b16 {%0,%1,%2,%3}, [%4];" \
                 : "=r"(r0), "=r"(r1), "=r"(r2), "=r"(r3) : "r"(addr))

#define CPA16(dst, src)                                                    \
    asm volatile("cp.async.cg.shared.global [%0], [%1], 16;"               \
                 :: "r"(dst), "l"(src))

// ---------------- prep: detect dtype + emit fp8 bytes [n][k] ----------------
// Every block samples the SAME first 4KB as f32: if the harness upcast the fp8
// weight to f32, all values are finite with |v|<1; if raw fp8 bytes, the
// reassembled f32s have random exponents. Deterministic, identical verdicts.
__global__ void LinearDSV3_prep(const void* __restrict__ w) {
    float4 probe = ((const float4*)w)[threadIdx.x];
    int ok = (fabsf(probe.x) < 1.0f) && (fabsf(probe.y) < 1.0f) &&
             (fabsf(probe.z) < 1.0f) && (fabsf(probe.w) < 1.0f);
    ok = __syncthreads_and(ok);

    int idx4 = blockIdx.x * 256 + threadIdx.x;
    uint32_t packed;
    if (ok) {
        float4 v = ((const float4*)w)[idx4];
        uint16_t lo, hi;
        asm("cvt.rn.satfinite.e4m3x2.f32 %0, %1, %2;" : "=h"(lo) : "f"(v.y), "f"(v.x));
        asm("cvt.rn.satfinite.e4m3x2.f32 %0, %1, %2;" : "=h"(hi) : "f"(v.w), "f"(v.z));
        packed = (uint32_t)lo | ((uint32_t)hi << 16);
    } else {
        packed = ((const uint32_t*)w)[idx4];
    }
    ((uint32_t*)g_w8)[idx4] = packed;
}

// ---------------- main: fused act-quant + fp8 GEMM, 1 barrier/iter ----------------

__global__ __launch_bounds__(THREADS, 1) void LinearDSV3_gemm(
    const float* __restrict__ x, const float* __restrict__ ws,
    float* __restrict__ y) {
    extern __shared__ char smraw[];
    const uint32_t S  = (uint32_t)__cvta_generic_to_shared(smraw);
    const uint32_t Ws = S + OFF_WS;
    const uint32_t Sc = S + OFF_SC;
    const uint32_t Ab = S + OFF_A;
    const uint32_t Bb = S + OFF_B;
    const uint32_t Xb = S + OFF_X;

    const int t = threadIdx.x;
    const int lane = t & 31;
    const int wid = t >> 5;
    const int wm = wid & 3;          // 4 M-warps x 32 rows
    const int wn = wid >> 2;         // 4 N-warps x 64 cols
    const int m0 = blockIdx.x * BM;

    const int lr = t >> 2;           // quant row 0..127
    const int q  = t & 3;            // quarter within 128-col block
    const int rs = lr & 7;           // row swizzle key

    if (t < 112) {
        float v = ws[t];
        asm volatile("st.shared.f32 [%0], %1;" :: "r"(Ws + t * 4), "f"(v));
    }

    // ---- async issuers (swizzled smem targets) ----
    auto issue_x = [&](int kb, int buf) {
#pragma unroll
        for (int j = 0; j < 8; ++j) {
            int c = t + j * THREADS;               // 0..4095
            int row = c >> 5, u = c & 31;
            int phys = (u & 24) | ((u & 7) ^ (row & 7));
            uint32_t dst = Xb + (uint32_t)(buf * 65536 + row * 512 + phys * 16);
            const void* src = x + (size_t)(m0 + row) * K_DIM + kb * 128 + u * 4;
            CPA16(dst, src);
        }
    };
    auto issue_B = [&](int kb, int buf) {
#pragma unroll
        for (int j = 0; j < 4; ++j) {
            int c = t + j * THREADS;               // 0..2047
            int n = c >> 3, u = c & 7;
            uint32_t dst = Bb + (uint32_t)(buf * 32768 + n * 128 + ((u ^ (n & 7)) * 16));
            const void* src = g_w8 + (size_t)n * K_DIM + kb * 128 + u * 16;
            CPA16(dst, src);
        }
    };
    // quant x block resident in X[buf] -> A[buf], Sc[buf]
    auto quant = [&](int buf) {
        const uint32_t xbase = Xb + (uint32_t)(buf * 65536 + lr * 512 + q * 128);
        float4 v[8];
#pragma unroll
        for (int j = 0; j < 8; ++j) {
            uint32_t addr = xbase + (uint32_t)((j ^ rs) << 4);
            asm volatile("ld.shared.v4.f32 {%0,%1,%2,%3}, [%4];"
                         : "=f"(v[j].x), "=f"(v[j].y), "=f"(v[j].z), "=f"(v[j].w)
                         : "r"(addr));
        }
        float am = 0.0f;
#pragma unroll
        for (int j = 0; j < 8; ++j) {
            am = fmaxf(am, fabsf(v[j].x)); am = fmaxf(am, fabsf(v[j].y));
            am = fmaxf(am, fabsf(v[j].z)); am = fmaxf(am, fabsf(v[j].w));
        }
        am = fmaxf(am, __shfl_xor_sync(0xFFFFFFFFu, am, 1));
        am = fmaxf(am, __shfl_xor_sync(0xFFFFFFFFu, am, 2));
        const float s = fmaxf(am, 1e-8f) / 448.0f;   // matches reference
        const float inv = 1.0f / s;
        uint32_t qo[8];
#pragma unroll
        for (int j = 0; j < 8; ++j)
            qo[j] = q2(v[j].x, v[j].y, inv) | (q2(v[j].z, v[j].w, inv) << 16);
        const uint32_t abase = Ab + (uint32_t)(buf * 16384 + lr * 128);
        const uint32_t u0 = (uint32_t)((2 * q) ^ rs);
        asm volatile("st.shared.v4.b32 [%0], {%1,%2,%3,%4};"
                     :: "r"(abase + u0 * 16), "r"(qo[0]), "r"(qo[1]), "r"(qo[2]), "r"(qo[3]));
        asm volatile("st.shared.v4.b32 [%0], {%1,%2,%3,%4};"
                     :: "r"(abase + (u0 ^ 1u) * 16), "r"(qo[4]), "r"(qo[5]), "r"(qo[6]), "r"(qo[7]));
        if (q == 0)
            asm volatile("st.shared.f32 [%0], %1;"
                         :: "r"(Sc + (uint32_t)(buf * 512 + lr * 4)), "f"(s));
    };

    // per-lane MMA base addresses (swizzle keys row&7 == lane-derived)
    const uint32_t a_base = Ab + (uint32_t)((wm * 32 + (lane & 15)) * 128);
    uint32_t a_pu[4];
#pragma unroll
    for (int ks = 0; ks < 4; ++ks)
        a_pu[ks] = (uint32_t)(((2 * ks + (lane >> 4)) ^ (lane & 7)) * 16);
    const uint32_t b_base = Bb + (uint32_t)((wn * 64 + (lane & 7)) * 128);
    const uint32_t b_pu1 = (uint32_t)(((lane >> 3) ^ (lane & 7)) * 16);
    const uint32_t b_pu2 = b_pu1 ^ 64u;

    // ---- prologue ----
    issue_B(0, 0); issue_x(0, 0);
    asm volatile("cp.async.commit_group;");
    issue_x(1, 1);
    asm volatile("cp.async.commit_group;");
    asm volatile("cp.async.wait_group 1;");   // {B0, X0} done
    __syncthreads();
    quant(0);

    float acc[2][8][4];
#pragma unroll
    for (int a = 0; a < 2; ++a)
#pragma unroll
        for (int b = 0; b < 8; ++b)
#pragma unroll
            for (int c = 0; c < 4; ++c) acc[a][b][c] = 0.0f;

#pragma unroll 1
    for (int kb = 0; kb < NKB; ++kb) {
        const int st = kb & 1;

        asm volatile("cp.async.wait_group 0;");
        __syncthreads();   // publishes: A[st] quant stores, B[st]+X[st^1] async data

        // issue next stage (targets' last readers all finished pre-barrier)
        if (kb + 1 < NKB) issue_B(kb + 1, st ^ 1);
        if (kb + 2 < NKB) issue_x(kb + 2, st);
        asm volatile("cp.async.commit_group;");

        // quant(kb+1) and MMA(kb) share one barrier-free region -> warps overlap
        if (kb + 1 < NKB) quant(st ^ 1);

        float sw;
        asm volatile("ld.shared.f32 %0, [%1];"
                     : "=f"(sw) : "r"(Ws + (uint32_t)(((wn >> 1) * NKB + kb) * 4)));

#pragma unroll
        for (int mt = 0; mt < 2; ++mt) {
            uint32_t af[16];
            const uint32_t am_addr = a_base + (uint32_t)(st * 16384 + mt * 2048);
#pragma unroll
            for (int ks = 0; ks < 4; ++ks) {
                uint32_t* r = af + 4 * ks;
                LDSM4(r[0], r[1], r[2], r[3], am_addr + a_pu[ks]);
            }
            float sa0, sa1;
            {
                uint32_t r0 = (uint32_t)(wm * 32 + mt * 16 + (lane >> 2));
                asm volatile("ld.shared.f32 %0, [%1];"
                             : "=f"(sa0) : "r"(Sc + (uint32_t)(st * 512) + r0 * 4));
                asm volatile("ld.shared.f32 %0, [%1];"
                             : "=f"(sa1) : "r"(Sc + (uint32_t)(st * 512) + (r0 + 8) * 4));
            }
            const float s0 = sa0 * sw, s1 = sa1 * sw;
#pragma unroll
            for (int nt = 0; nt < 8; ++nt) {
                const uint32_t bn = b_base + (uint32_t)(st * 32768 + nt * 1024);
                uint32_t b0, b1, b2, b3, b4, b5, b6, b7;
                LDSM4(b0, b1, b2, b3, bn + b_pu1);   // ks0:(b0,b1) ks1:(b2,b3)
                LDSM4(b4, b5, b6, b7, bn + b_pu2);   // ks2:(b4,b5) ks3:(b6,b7)
                float t0[4] = {0.f, 0.f, 0.f, 0.f};
                qmma(t0, af + 0,  b0, b1);
                qmma(t0, af + 4,  b2, b3);
                qmma(t0, af + 8,  b4, b5);
                qmma(t0, af + 12, b6, b7);
                acc[mt][nt][0] += s0 * t0[0];
                acc[mt][nt][1] += s0 * t0[1];
                acc[mt][nt][2] += s1 * t0[2];
                acc[mt][nt][3] += s1 * t0[3];
            }
        }
    }

    // ---- epilogue ----
    const int mwb = m0 + wm * 32;
#pragma unroll
    for (int mt = 0; mt < 2; ++mt) {
        int r0 = mwb + mt * 16 + (lane >> 2);
#pragma unroll
        for (int nt = 0; nt < 8; ++nt) {
            int c = wn * 64 + nt * 8 + (lane & 3) * 2;
            float2 v0 = make_float2(acc[mt][nt][0], acc[mt][nt][1]);
            float2 v1 = make_float2(acc[mt][nt][2], acc[mt][nt][3]);
            *(float2*)(y + (size_t)r0 * N_DIM + c) = v0;
            *(float2*)(y + (size_t)(r0 + 8) * N_DIM + c) = v1;
        }
    }
}

// ---------------- launch ----------------

extern "C" void kernel_launch(void* const* d_in, const int* in_sizes, int n_in,
                              void* d_out, int out_size) {
    const float* x  = (const float*)d_in[0];
    const void*  w  = d_in[1];
    const float* ws = (const float*)d_in[2];
    float*       y  = (float*)d_out;

    const int M = in_sizes[0] / K_DIM;   // 16384

    cudaFuncSetAttribute(LinearDSV3_gemm,
                         cudaFuncAttributeMaxDynamicSharedMemorySize, SMEM_BYTES);

    LinearDSV3_prep<<<(N_DIM * K_DIM) / 1024, 256>>>(w);
    LinearDSV3_gemm<<<M / BM, THREADS, SMEM_BYTES>>>(x, ws, y);
}

// round 16
// speedup vs baseline: 1.1323x; 1.1323x over previous
#include <cuda_runtime.h>
#include <cstdint>

#define K_DIM 7168
#define N_DIM 256
#define BM 128
#define NKB 56
#define THREADS 1024

// smem layout (bytes)
#define OFF_WS 0              // 112 f32 weight scales
#define OFF_SC 512            // 2 stages x 128 f32 act scales
#define OFF_A  1536           // 2 x 16384 (128 rows x 128B fp8, swizzled)
#define OFF_B  34304          // 2 x 32768 (256 rows x 128B fp8, swizzled)
#define SMEM_BYTES 99840

__device__ __align__(16) uint8_t g_w8[(size_t)N_DIM * K_DIM];

// ---------------- helpers ----------------

__device__ __forceinline__ uint32_t q2(float a, float b, float inv) {
    uint16_t p;
    asm("cvt.rn.satfinite.e4m3x2.f32 %0, %1, %2;"
        : "=h"(p) : "f"(b * inv), "f"(a * inv));
    return (uint32_t)p;
}

__device__ __forceinline__ void qmma(float* c, const uint32_t* a,
                                     uint32_t b0, uint32_t b1) {
    asm volatile(
        "mma.sync.aligned.m16n8k32.row.col.f32.e4m3.e4m3.f32 "
        "{%0,%1,%2,%3}, {%4,%5,%6,%7}, {%8,%9}, {%0,%1,%2,%3};"
        : "+f"(c[0]), "+f"(c[1]), "+f"(c[2]), "+f"(c[3])
        : "r"(a[0]), "r"(a[1]), "r"(a[2]), "r"(a[3]), "r"(b0), "r"(b1));
}

#define LDSM4(r0, r1, r2, r3, addr)                                        \
    asm volatile("ldmatrix.sync.aligned.m8n8.x4.shared.b16 {%0,%1,%2,%3}, [%4];" \
                 : "=r"(r0), "=r"(r1), "=r"(r2), "=r"(r3) : "r"(addr))

#define CPA16(dst, src)                                                    \
    asm volatile("cp.async.cg.shared.global [%0], [%1], 16;"               \
                 :: "r"(dst), "l"(src))

// ---------------- prep: detect dtype + emit fp8 bytes [n][k] ----------------
// Every block samples the SAME first 4KB as f32: a harness-upcast f32 buffer
// has all |v|<1; raw fp8 bytes reassembled as f32 have random exponents.
// Deterministic, identical verdicts across blocks.
__global__ void LinearDSV3_prep(const void* __restrict__ w) {
    float4 probe = ((const float4*)w)[threadIdx.x];
    int ok = (fabsf(probe.x) < 1.0f) && (fabsf(probe.y) < 1.0f) &&
             (fabsf(probe.z) < 1.0f) && (fabsf(probe.w) < 1.0f);
    ok = __syncthreads_and(ok);

    int idx4 = blockIdx.x * 256 + threadIdx.x;
    uint32_t packed;
    if (ok) {
        float4 v = ((const float4*)w)[idx4];
        uint16_t lo, hi;
        asm("cvt.rn.satfinite.e4m3x2.f32 %0, %1, %2;" : "=h"(lo) : "f"(v.y), "f"(v.x));
        asm("cvt.rn.satfinite.e4m3x2.f32 %0, %1, %2;" : "=h"(hi) : "f"(v.w), "f"(v.z));
        packed = (uint32_t)lo | ((uint32_t)hi << 16);
    } else {
        packed = ((const uint32_t*)w)[idx4];
    }
    ((uint32_t*)g_w8)[idx4] = packed;
}

// ---------------- main: fused act-quant + fp8 GEMM, 1024 threads ----------------

__global__ __launch_bounds__(THREADS, 1) void LinearDSV3_gemm(
    const float* __restrict__ x, const float* __restrict__ ws,
    float* __restrict__ y) {
    extern __shared__ char smraw[];
    const uint32_t S  = (uint32_t)__cvta_generic_to_shared(smraw);
    const uint32_t Ws = S + OFF_WS;
    const uint32_t Sc = S + OFF_SC;
    const uint32_t Ab = S + OFF_A;
    const uint32_t Bb = S + OFF_B;

    const int t = threadIdx.x;
    const int lane = t & 31;
    const int wid = t >> 5;          // 0..31
    const int wm = wid & 7;          // 8 M-warps x 16 rows
    const int wn = wid >> 3;         // 4 N-warps x 64 cols
    const int m0 = blockIdx.x * BM;

    const int lr = t >> 3;           // quant row 0..127 (8 threads/row)
    const int q8 = t & 7;            // 16B unit within 128B row
    const float* xr = x + (size_t)(m0 + lr) * K_DIM + q8 * 16;

    if (t < 112) {
        float v = ws[t];
        asm volatile("st.shared.f32 [%0], %1;" :: "r"(Ws + t * 4), "f"(v));
    }

    auto issue_B = [&](int kb, int buf) {
#pragma unroll
        for (int j = 0; j < 2; ++j) {
            int c = t + j * THREADS;               // 0..2047
            int n = c >> 3, u = c & 7;
            uint32_t dst = Bb + (uint32_t)(buf * 32768 + n * 128 + ((u ^ (n & 7)) * 16));
            const void* src = g_w8 + (size_t)n * K_DIM + kb * 128 + u * 16;
            CPA16(dst, src);
        }
    };

    // per-lane MMA addresses (formulas identical to validated R13 mapping)
    const uint32_t a_base = Ab + (uint32_t)((wm * 16 + (lane & 15)) * 128);
    uint32_t a_pu[4];
#pragma unroll
    for (int ks = 0; ks < 4; ++ks)
        a_pu[ks] = (uint32_t)(((2 * ks + (lane >> 4)) ^ (lane & 7)) * 16);
    const uint32_t b_base = Bb + (uint32_t)((wn * 64 + (lane & 7)) * 128);
    uint32_t b_pu[2];
    b_pu[0] = (uint32_t)((((lane >> 3)) ^ (lane & 7)) * 16);
    b_pu[1] = (uint32_t)((((lane >> 3) + 4) ^ (lane & 7)) * 16);

    // ---- prologue: B(0) in flight; amax pass for block 0 ----
    issue_B(0, 0);
    asm volatile("cp.async.commit_group;");

    float am_cur;
    {
        float4 p0 = __ldg((const float4*)(xr));
        float4 p1 = __ldg((const float4*)(xr + 4));
        float4 p2 = __ldg((const float4*)(xr + 8));
        float4 p3 = __ldg((const float4*)(xr + 12));
        float a0 = fmaxf(fmaxf(fabsf(p0.x), fabsf(p0.y)), fmaxf(fabsf(p0.z), fabsf(p0.w)));
        float a1 = fmaxf(fmaxf(fabsf(p1.x), fabsf(p1.y)), fmaxf(fabsf(p1.z), fabsf(p1.w)));
        float a2 = fmaxf(fmaxf(fabsf(p2.x), fabsf(p2.y)), fmaxf(fabsf(p2.z), fabsf(p2.w)));
        float a3 = fmaxf(fmaxf(fabsf(p3.x), fabsf(p3.y)), fmaxf(fabsf(p3.z), fabsf(p3.w)));
        float am = fmaxf(fmaxf(a0, a1), fmaxf(a2, a3));
        am = fmaxf(am, __shfl_xor_sync(0xFFFFFFFFu, am, 1));
        am = fmaxf(am, __shfl_xor_sync(0xFFFFFFFFu, am, 2));
        am = fmaxf(am, __shfl_xor_sync(0xFFFFFFFFu, am, 4));
        am_cur = am;
    }

    float acc[8][4];
#pragma unroll
    for (int b = 0; b < 8; ++b)
#pragma unroll
        for (int c = 0; c < 4; ++c) acc[b][c] = 0.0f;

#pragma unroll 1
    for (int kb = 0; kb < NKB; ++kb) {
        const int st = kb & 1;

        // ---- quant(kb): scale known; values re-read (L1 hits) ----
        const float s = fmaxf(am_cur, 1e-8f) / 448.0f;   // matches reference
        const float inv = 1.0f / s;
        {
            const float* xp = xr + kb * 128;
            float4 v0 = __ldg((const float4*)(xp));
            float4 v1 = __ldg((const float4*)(xp + 4));
            float4 v2 = __ldg((const float4*)(xp + 8));
            float4 v3 = __ldg((const float4*)(xp + 12));
            uint32_t o0 = q2(v0.x, v0.y, inv) | (q2(v0.z, v0.w, inv) << 16);
            uint32_t o1 = q2(v1.x, v1.y, inv) | (q2(v1.z, v1.w, inv) << 16);
            uint32_t o2 = q2(v2.x, v2.y, inv) | (q2(v2.z, v2.w, inv) << 16);
            uint32_t o3 = q2(v3.x, v3.y, inv) | (q2(v3.z, v3.w, inv) << 16);
            uint32_t adst = Ab + (uint32_t)(st * 16384 + lr * 128 + ((q8 ^ (lr & 7)) * 16));
            asm volatile("st.shared.v4.b32 [%0], {%1,%2,%3,%4};"
                         :: "r"(adst), "r"(o0), "r"(o1), "r"(o2), "r"(o3));
        }
        if (q8 == 0)
            asm volatile("st.shared.f32 [%0], %1;"
                         :: "r"(Sc + (uint32_t)(st * 512 + lr * 4)), "f"(s));

        // ---- pass1: stream x(kb+1), amax only (loads issued pre-barrier) ----
        float4 p0, p1, p2, p3;
        if (kb + 1 < NKB) {
            const float* xn = xr + (kb + 1) * 128;
            p0 = __ldg((const float4*)(xn));
            p1 = __ldg((const float4*)(xn + 4));
            p2 = __ldg((const float4*)(xn + 8));
            p3 = __ldg((const float4*)(xn + 12));
        }

        asm volatile("cp.async.wait_group 0;");   // B(kb) resident
        __syncthreads();                          // A(kb)+scales visible; MMA(kb-1) done

        if (kb + 1 < NKB) {
            issue_B(kb + 1, st ^ 1);
            asm volatile("cp.async.commit_group;");
        }

        if (kb + 1 < NKB) {
            float a0 = fmaxf(fmaxf(fabsf(p0.x), fabsf(p0.y)), fmaxf(fabsf(p0.z), fabsf(p0.w)));
            float a1 = fmaxf(fmaxf(fabsf(p1.x), fabsf(p1.y)), fmaxf(fabsf(p1.z), fabsf(p1.w)));
            float a2 = fmaxf(fmaxf(fabsf(p2.x), fabsf(p2.y)), fmaxf(fabsf(p2.z), fabsf(p2.w)));
            float a3 = fmaxf(fmaxf(fabsf(p3.x), fabsf(p3.y)), fmaxf(fabsf(p3.z), fabsf(p3.w)));
            float am = fmaxf(fmaxf(a0, a1), fmaxf(a2, a3));
            am = fmaxf(am, __shfl_xor_sync(0xFFFFFFFFu, am, 1));
            am = fmaxf(am, __shfl_xor_sync(0xFFFFFFFFu, am, 2));
            am = fmaxf(am, __shfl_xor_sync(0xFFFFFFFFu, am, 4));
            am_cur = am;
        }

        // ---- MMA(kb): warp tile 16(M) x 64(N) x 128(K) ----
        float sw;
        asm volatile("ld.shared.f32 %0, [%1];"
                     : "=f"(sw) : "r"(Ws + (uint32_t)(((wn >> 1) * NKB + kb) * 4)));
        float sa0, sa1;
        {
            uint32_t r0 = (uint32_t)(wm * 16 + (lane >> 2));
            asm volatile("ld.shared.f32 %0, [%1];"
                         : "=f"(sa0) : "r"(Sc + (uint32_t)(st * 512) + r0 * 4));
            asm volatile("ld.shared.f32 %0, [%1];"
                         : "=f"(sa1) : "r"(Sc + (uint32_t)(st * 512) + (r0 + 8) * 4));
        }
        const float s0 = sa0 * sw, s1 = sa1 * sw;
        const uint32_t ab = a_base + (uint32_t)(st * 16384);
        const uint32_t bbs = b_base + (uint32_t)(st * 32768);

#pragma unroll
        for (int kh = 0; kh < 2; ++kh) {
            uint32_t aA[4], aB[4];
            LDSM4(aA[0], aA[1], aA[2], aA[3], ab + a_pu[2 * kh]);
            LDSM4(aB[0], aB[1], aB[2], aB[3], ab + a_pu[2 * kh + 1]);
#pragma unroll
            for (int nt = 0; nt < 8; ++nt) {
                uint32_t b0, b1, b2, b3;
                LDSM4(b0, b1, b2, b3, bbs + (uint32_t)(nt * 1024) + b_pu[kh]);
                float t0[4] = {0.f, 0.f, 0.f, 0.f};
                qmma(t0, aA, b0, b1);
                qmma(t0, aB, b2, b3);
                acc[nt][0] = fmaf(s0, t0[0], acc[nt][0]);
                acc[nt][1] = fmaf(s0, t0[1], acc[nt][1]);
                acc[nt][2] = fmaf(s1, t0[2], acc[nt][2]);
                acc[nt][3] = fmaf(s1, t0[3], acc[nt][3]);
            }
        }
    }

    // ---- epilogue ----
    {
        int r0 = m0 + wm * 16 + (lane >> 2);
#pragma unroll
        for (int nt = 0; nt < 8; ++nt) {
            int c = wn * 64 + nt * 8 + (lane & 3) * 2;
            float2 v0 = make_float2(acc[nt][0], acc[nt][1]);
            float2 v1 = make_float2(acc[nt][2], acc[nt][3]);
            *(float2*)(y + (size_t)r0 * N_DIM + c) = v0;
            *(float2*)(y + (size_t)(r0 + 8) * N_DIM + c) = v1;
        }
    }
}

// ---------------- launch ----------------

extern "C" void kernel_launch(void* const* d_in, const int* in_sizes, int n_in,
                              void* d_out, int out_size) {
    const float* x  = (const float*)d_in[0];
    const void*  w  = d_in[1];
    const float* ws = (const float*)d_in[2];
    float*       y  = (float*)d_out;

    const int M = in_sizes[0] / K_DIM;   // 16384

    cudaFuncSetAttribute(LinearDSV3_gemm,
                         cudaFuncAttributeMaxDynamicSharedMemorySize, SMEM_BYTES);

    LinearDSV3_prep<<<(N_DIM * K_DIM) / 1024, 256>>>(w);
    LinearDSV3_gemm<<<M / BM, THREADS, SMEM_BYTES>>>(x, ws, y);
}